// round 9
// baseline (speedup 1.0000x reference)
#include <cuda_runtime.h>
#include <cuda_bf16.h>
#include <math.h>
#include <stdint.h>

#define B_ 4
#define C_ 256
#define H_ 128
#define W_ 128
#define HW_ (H_*W_)
#define NPIX_ (B_*HW_)
#define NT64 (NPIX_/64)      // 1024 GEMM tiles, 64 pixels each

typedef unsigned int u32;

// ---------------- global scratch ----------------
__device__ float g_xt[(size_t)NPIX_ * C_];                                 // 64 MB
__device__ __align__(16) __nv_bfloat16 gQ[(size_t)NT64 * 2 * 64 * 256];    // 64 MB
__device__ __align__(16) __nv_bfloat16 gX[(size_t)NT64 * 2 * 64 * 256];    // 64 MB
__device__ __align__(16) __nv_bfloat16 gW[2 * 2 * 256 * 256];              // 512 KB
__device__ __align__(16) float gP[(size_t)NT64 * 2 * 64 * 128];            // 64 MB (parked Q)
__device__ __align__(16) float gS[(size_t)NT64 * 2 * 5 * 64];              // 2.6 MB (partial stats)

// ---------------- PTX helpers ----------------
__device__ __forceinline__ u32 smem_u32(const void* p) {
    u32 a; asm("{ .reg .u64 t; cvta.to.shared.u64 t, %1; cvt.u32.u64 %0, t; }"
               : "=r"(a) : "l"(p));
    return a;
}
__device__ __forceinline__ void ldmx4(u32 addr, u32* r) {
    asm volatile("ldmatrix.sync.aligned.m8n8.x4.shared.b16 {%0,%1,%2,%3}, [%4];"
                 : "=r"(r[0]), "=r"(r[1]), "=r"(r[2]), "=r"(r[3]) : "r"(addr));
}
__device__ __forceinline__ void cpa16(u32 dst, const void* src) {
    asm volatile("cp.async.cg.shared.global [%0], [%1], 16;" :: "r"(dst), "l"(src));
}
#define CP_COMMIT() asm volatile("cp.async.commit_group;" ::: "memory")
#define CP_WAIT(n)  asm volatile("cp.async.wait_group %0;" :: "n"(n) : "memory")

__device__ __forceinline__ void mma_bf16(float* d, const u32* a, u32 b0, u32 b1) {
    asm volatile(
        "mma.sync.aligned.m16n8k16.row.col.f32.bf16.bf16.f32 "
        "{%0,%1,%2,%3},{%4,%5,%6,%7},{%8,%9},{%0,%1,%2,%3};"
        : "+f"(d[0]), "+f"(d[1]), "+f"(d[2]), "+f"(d[3])
        : "r"(a[0]), "r"(a[1]), "r"(a[2]), "r"(a[3]), "r"(b0), "r"(b1));
}

// ---------------------------------------------------------------------------
// Transpose x -> g_xt (NHWC fp32) AND gX (bf16 hi/lo, GEMM tile layout)
// ---------------------------------------------------------------------------
__global__ void k_tx(const float* __restrict__ x) {
    __shared__ float t[32][33];
    int b = blockIdx.z, s0 = blockIdx.x * 32, c0 = blockIdx.y * 32;
    int tx = threadIdx.x, ty = threadIdx.y;
    const float* xi = x + (size_t)b * C_ * HW_;
    float* xo = g_xt + (size_t)b * HW_ * C_;
#pragma unroll
    for (int i = 0; i < 32; i += 8)
        t[ty + i][tx] = xi[(size_t)(c0 + ty + i) * HW_ + s0 + tx];
    __syncthreads();
#pragma unroll
    for (int i = 0; i < 32; i += 8) {
        float v = t[tx][ty + i];
        int s = s0 + ty + i;
        xo[(size_t)s * C_ + c0 + tx] = v;
        int gp = b * HW_ + s;
        size_t tb = (size_t)(gp >> 6) * 32768 + (size_t)(gp & 63) * 256 + c0 + tx;
        __nv_bfloat16 h = __float2bfloat16_rn(v);
        gX[tb]         = h;
        gX[tb + 16384] = __float2bfloat16_rn(v - __bfloat162float(h));
    }
}

// ---------------------------------------------------------------------------
// Weight prep: w[o][c] fp32 -> gW[g][plane][o][k] bf16 (hi/lo split)
// ---------------------------------------------------------------------------
__global__ void k_wprep(const float* __restrict__ w0, const float* __restrict__ w1) {
    int g = blockIdx.x;
    int o = threadIdx.x;
    const float* w = g ? w1 : w0;
    __nv_bfloat16* hi = gW + ((size_t)(g * 2 + 0) * 256 + o) * 256;
    __nv_bfloat16* lo = gW + ((size_t)(g * 2 + 1) * 256 + o) * 256;
    for (int k = 0; k < 256; k++) {
        float a = w[o * 256 + k];
        __nv_bfloat16 h = __float2bfloat16_rn(a);
        hi[k] = h;
        lo[k] = __float2bfloat16_rn(a - __bfloat162float(h));
    }
}

// ---------------------------------------------------------------------------
// Gather: deformable 3x3 max-unfold -> gQ (bf16 hi/lo tiles)
// ---------------------------------------------------------------------------
__device__ __forceinline__ void split_store4(__nv_bfloat16* pHi, __nv_bfloat16* pLo, float4 v) {
    __nv_bfloat16 h0 = __float2bfloat16_rn(v.x), h1 = __float2bfloat16_rn(v.y);
    __nv_bfloat16 h2 = __float2bfloat16_rn(v.z), h3 = __float2bfloat16_rn(v.w);
    __nv_bfloat162 a = __halves2bfloat162(h0, h1), b = __halves2bfloat162(h2, h3);
    __nv_bfloat162 c = __halves2bfloat162(
        __float2bfloat16_rn(v.x - __bfloat162float(h0)),
        __float2bfloat16_rn(v.y - __bfloat162float(h1)));
    __nv_bfloat162 d = __halves2bfloat162(
        __float2bfloat16_rn(v.z - __bfloat162float(h2)),
        __float2bfloat16_rn(v.w - __bfloat162float(h3)));
    uint2 hv, lv;
    hv.x = *(u32*)&a; hv.y = *(u32*)&b;
    lv.x = *(u32*)&c; lv.y = *(u32*)&d;
    *(uint2*)pHi = hv;
    *(uint2*)pLo = lv;
}

__global__ __launch_bounds__(256)
void k_gather(const float* __restrict__ offset) {
    __shared__ float offs[18 * 32];
    const int tid  = threadIdx.x;
    const int base = blockIdx.x * 32;
    const int b    = base / HW_;
    const int rem  = base % HW_;
    const int y    = rem / W_;
    const int x0   = rem % W_;

    for (int i = tid; i < 18 * 32; i += 256) {
        int j = i >> 5, p = i & 31;
        offs[i] = offset[((size_t)b * 18 + j) * HW_ + y * W_ + x0 + p];
    }
    __syncthreads();

    const float* xtb = g_xt + (size_t)b * HW_ * C_;
    const int sub = tid & 7;
    const int p   = tid >> 3;
    const int pxi = x0 + p;
    const int tile = blockIdx.x >> 1;
    const int r    = ((blockIdx.x & 1) << 5) + p;

    float4 qm[8];
#pragma unroll
    for (int i = 0; i < 8; i++) { qm[i].x = qm[i].y = qm[i].z = qm[i].w = -3.4e38f; }

#pragma unroll
    for (int k = 0; k < 9; k++) {
        const int kh = k / 3 - 1, kw = k % 3 - 1;
        float py  = (float)(y + kh)   + offs[(2 * k) * 32 + p];
        float pxx = (float)(pxi + kw) + offs[(2 * k + 1) * 32 + p];
        float fy = floorf(py), fx = floorf(pxx);
        float wy = py - fy, wx = pxx - fx;
        int iy = (int)fy, ix = (int)fx;

        float4 acc[8];
#pragma unroll
        for (int i = 0; i < 8; i++) { acc[i].x = acc[i].y = acc[i].z = acc[i].w = 0.f; }

        float cw[4] = { (1.f - wy) * (1.f - wx), (1.f - wy) * wx,
                        wy * (1.f - wx),         wy * wx };
        int cy[4] = { iy, iy, iy + 1, iy + 1 };
        int cx[4] = { ix, ix + 1, ix, ix + 1 };
#pragma unroll
        for (int c4 = 0; c4 < 4; c4++) {
            if (cy[c4] >= 0 && cy[c4] < H_ && cx[c4] >= 0 && cx[c4] < W_) {
                const float4* cp = (const float4*)(xtb + (size_t)(cy[c4] * W_ + cx[c4]) * C_);
                float w = cw[c4];
#pragma unroll
                for (int i = 0; i < 8; i++) {
                    float4 v = cp[sub + 8 * i];
                    acc[i].x = fmaf(w, v.x, acc[i].x);
                    acc[i].y = fmaf(w, v.y, acc[i].y);
                    acc[i].z = fmaf(w, v.z, acc[i].z);
                    acc[i].w = fmaf(w, v.w, acc[i].w);
                }
            }
        }
#pragma unroll
        for (int i = 0; i < 8; i++) {
            qm[i].x = fmaxf(qm[i].x, acc[i].x);
            qm[i].y = fmaxf(qm[i].y, acc[i].y);
            qm[i].z = fmaxf(qm[i].z, acc[i].z);
            qm[i].w = fmaxf(qm[i].w, acc[i].w);
        }
    }

    size_t tbase = (size_t)tile * 32768 + (size_t)r * 256;
#pragma unroll
    for (int i = 0; i < 8; i++) {
        int c = 4 * (sub + 8 * i);
        split_store4(gQ + tbase + c, gQ + tbase + 16384 + c, qm[i]);
    }
}

// ---------------------------------------------------------------------------
// GEMM: M64 x N128 per CTA (half the output channels), 256 threads (8 warps,
// 2m x 4n), 3 CTAs/SM. 3-stage cp.async pipeline. Partial stats -> gS.
// ---------------------------------------------------------------------------
#define ARS 48
#define SOFF_BIAS  0        // 256 f = 1024 B
#define SOFF_STATS 1024     // 4*5*64 f = 5120 B
#define SOFF_A     6272     // 3 stages x 6144 B
#define SOFF_B     24704    // 3 stages x 12288 B
#define SMEM_TOTAL 61568

__global__ __launch_bounds__(256, 3)
void k_gemm(const float* __restrict__ gb0, const float* __restrict__ gb1,
            float* __restrict__ out) {
    extern __shared__ unsigned char sm[];
    float* bias  = (float*)(sm + SOFF_BIAS);    // [128 q][128 k]
    float* stats = (float*)(sm + SOFF_STATS);
    const u32 smb = smem_u32(sm);
    const u32 smA = smb + SOFF_A;
    const u32 smB = smb + SOFF_B;

    const int tid = threadIdx.x, lane = tid & 31, wid = tid >> 5;
    const int mw = wid >> 2, nw = wid & 3;
    const int tile = blockIdx.x;
    const int h = blockIdx.y;          // N half

    bias[tid] = (tid < 128) ? gb0[h * 128 + tid] : gb1[h * 128 + tid - 128];

    // staging decomposition
    const int aPl = tid >> 7, aRow = (tid >> 1) & 63, aHf = tid & 1;
    const u32 aDst0 = smA + aPl * 3072 + aRow * ARS + aHf * 16;

    // ldmatrix lane addressing
    const int aLRow = lane & 15, aLCol = (lane >> 4) * 16;
    const int bLRow = ((lane >> 4) << 3) + (lane & 7), bLCol = ((lane >> 3) & 1) * 16;

    float* parkP = gP + ((size_t)tile * 2 + h) * 64 * 128;

    for (int ph = 0; ph < 2; ph++) {
        const __nv_bfloat16* Ab = (ph ? gX : gQ) + (size_t)tile * 32768;
        const __nv_bfloat16* Bb = gW + (size_t)ph * 131072 + h * 128 * 256;
        const __nv_bfloat16* aSrc = Ab + aPl * 16384 + aRow * 256 + aHf * 8;

        float acc[2][4][4];
#pragma unroll
        for (int s = 0; s < 2; s++)
#pragma unroll
            for (int t = 0; t < 4; t++)
#pragma unroll
                for (int j = 0; j < 4; j++) acc[s][t][j] = 0.f;

        // prologue: stage 0 and 1
#pragma unroll
        for (int st = 0; st < 2; st++) {
            cpa16(aDst0 + st * 6144, aSrc + st * 16);
#pragma unroll
            for (int i = 0; i < 2; i++) {
                int idx = tid + i * 256;
                int pl = idx >> 8, row = (idx >> 1) & 127, hf = idx & 1;
                cpa16(smB + st * 12288 + pl * 6144 + row * ARS + hf * 16,
                      Bb + pl * 65536 + row * 256 + st * 16 + hf * 8);
            }
            CP_COMMIT();
        }

        for (int ks = 0; ks < 16; ks++) {
            if (ks < 14) { CP_WAIT(1); } else { CP_WAIT(0); }
            __syncthreads();

            const int cur = ks % 3;
            const u32 Ac = smA + cur * 6144;
            const u32 Bc = smB + cur * 12288;

            u32 ah[2][4], al[2][4];
#pragma unroll
            for (int s = 0; s < 2; s++) {
                u32 arow = (u32)(mw * 32 + s * 16 + aLRow);
                ldmx4(Ac + arow * ARS + aLCol, ah[s]);
                ldmx4(Ac + 3072 + arow * ARS + aLCol, al[s]);
            }
#pragma unroll
            for (int tt = 0; tt < 2; tt++) {
                u32 brow = (u32)(nw * 32 + tt * 16 + bLRow);
                u32 bh[4], bl[4];
                ldmx4(Bc + brow * ARS + bLCol, bh);
                ldmx4(Bc + 6144 + brow * ARS + bLCol, bl);
#pragma unroll
                for (int half = 0; half < 2; half++) {
                    int t = tt * 2 + half;
                    u32 b0h = bh[half * 2], b1h = bh[half * 2 + 1];
                    u32 b0l = bl[half * 2], b1l = bl[half * 2 + 1];
#pragma unroll
                    for (int s = 0; s < 2; s++) {
                        mma_bf16(acc[s][t], ah[s], b0h, b1h);
                        mma_bf16(acc[s][t], ah[s], b0l, b1l);
                        mma_bf16(acc[s][t], al[s], b0h, b1h);
                    }
                }
            }

            if (ks < 14) {
                const int nst = (ks + 2) % 3;
                cpa16(aDst0 + nst * 6144, aSrc + (ks + 2) * 16);
#pragma unroll
                for (int i = 0; i < 2; i++) {
                    int idx = tid + i * 256;
                    int pl = idx >> 8, row = (idx >> 1) & 127, hf = idx & 1;
                    cpa16(smB + nst * 12288 + pl * 6144 + row * ARS + hf * 16,
                          Bb + pl * 65536 + row * 256 + (ks + 2) * 16 + hf * 8);
                }
                CP_COMMIT();
            }
        }
        __syncthreads();   // staging buffers reused by next phase

        if (ph == 0) {
            // park Q (+bias) in global
#pragma unroll
            for (int s = 0; s < 2; s++) {
                int r1 = mw * 32 + s * 16 + (lane >> 2);
#pragma unroll
                for (int t = 0; t < 4; t++) {
                    int n0 = nw * 32 + t * 8 + (lane & 3) * 2;
                    float2 v0 = make_float2(acc[s][t][0] + bias[n0], acc[s][t][1] + bias[n0 + 1]);
                    float2 v1 = make_float2(acc[s][t][2] + bias[n0], acc[s][t][3] + bias[n0 + 1]);
                    *(float2*)(parkP + r1 * 128 + n0) = v0;
                    *(float2*)(parkP + (r1 + 8) * 128 + n0) = v1;
                }
            }
        } else {
            // fold partial 5 stats per pixel over this N half
#pragma unroll
            for (int s = 0; s < 2; s++) {
                int r1 = mw * 32 + s * 16 + (lane >> 2);
                float st0[5] = {0, 0, 0, 0, 0}, st1[5] = {0, 0, 0, 0, 0};
#pragma unroll
                for (int t = 0; t < 4; t++) {
                    int n0 = nw * 32 + t * 8 + (lane & 3) * 2;
                    float bk0 = bias[128 + n0], bk1 = bias[128 + n0 + 1];
                    float2 q0 = *(float2*)(parkP + r1 * 128 + n0);
                    float2 q1 = *(float2*)(parkP + (r1 + 8) * 128 + n0);
                    float k0v = acc[s][t][0] + bk0, k1v = acc[s][t][1] + bk1;
                    float k2v = acc[s][t][2] + bk0, k3v = acc[s][t][3] + bk1;
                    st0[0] += q0.x + q0.y;  st0[1] += k0v + k1v;
                    st0[2] = fmaf(q0.x, q0.x, fmaf(q0.y, q0.y, st0[2]));
                    st0[3] = fmaf(k0v, k0v, fmaf(k1v, k1v, st0[3]));
                    st0[4] = fmaf(q0.x, k0v, fmaf(q0.y, k1v, st0[4]));
                    st1[0] += q1.x + q1.y;  st1[1] += k2v + k3v;
                    st1[2] = fmaf(q1.x, q1.x, fmaf(q1.y, q1.y, st1[2]));
                    st1[3] = fmaf(k2v, k2v, fmaf(k3v, k3v, st1[3]));
                    st1[4] = fmaf(q1.x, k2v, fmaf(q1.y, k3v, st1[4]));
                }
#pragma unroll
                for (int j = 0; j < 5; j++) {
                    st0[j] += __shfl_xor_sync(0xffffffffu, st0[j], 1);
                    st0[j] += __shfl_xor_sync(0xffffffffu, st0[j], 2);
                    st1[j] += __shfl_xor_sync(0xffffffffu, st1[j], 1);
                    st1[j] += __shfl_xor_sync(0xffffffffu, st1[j], 2);
                }
                if ((lane & 3) == 0) {
#pragma unroll
                    for (int j = 0; j < 5; j++) {
                        stats[(nw * 5 + j) * 64 + r1]     = st0[j];
                        stats[(nw * 5 + j) * 64 + r1 + 8] = st1[j];
                    }
                }
            }
            __syncthreads();
            if (tid < 64) {
                float* dst = gS + ((size_t)tile * 2 + h) * 5 * 64;
#pragma unroll
                for (int j = 0; j < 5; j++) {
                    float v = 0.f;
#pragma unroll
                    for (int w = 0; w < 4; w++) v += stats[(w * 5 + j) * 64 + tid];
                    dst[j * 64 + tid] = v;
                }
            }
        }
    }
}

// ---------------------------------------------------------------------------
// Final: combine N-half stats -> normalized dot
// ---------------------------------------------------------------------------
__global__ void k_final(float* __restrict__ out) {
    int p = blockIdx.x * 256 + threadIdx.x;
    int tile = p >> 6, r = p & 63;
    const float* s0 = gS + ((size_t)tile * 2 + 0) * 5 * 64;
    const float* s1 = gS + ((size_t)tile * 2 + 1) * 5 * 64;
    float sq  = s0[0 * 64 + r] + s1[0 * 64 + r];
    float sk  = s0[1 * 64 + r] + s1[1 * 64 + r];
    float sqq = s0[2 * 64 + r] + s1[2 * 64 + r];
    float skk = s0[3 * 64 + r] + s1[3 * 64 + r];
    float sqk = s0[4 * 64 + r] + s1[4 * 64 + r];
    const float inv = 1.f / 256.f;
    float num = sqk - sq * sk * inv;
    float dq  = sqq - sq * sq * inv + 1e-5f;
    float dk  = skk - sk * sk * inv + 1e-5f;
    out[p] = num * rsqrtf(dq) * rsqrtf(dk);
}

// ---------------------------------------------------------------------------
extern "C" void kernel_launch(void* const* d_in, const int* in_sizes, int n_in,
                              void* d_out, int out_size) {
    const float* x      = (const float*)d_in[0];
    const float* offset = (const float*)d_in[1];
    const float* w0     = (const float*)d_in[2];
    const float* b0     = (const float*)d_in[3];
    const float* w1     = (const float*)d_in[4];
    const float* b1     = (const float*)d_in[5];
    float* out = (float*)d_out;

    k_tx<<<dim3(HW_ / 32, C_ / 32, B_), dim3(32, 8)>>>(x);
    k_wprep<<<2, 256>>>(w0, w1);
    k_gather<<<NPIX_ / 32, 256>>>(offset);

    cudaFuncSetAttribute(k_gemm, cudaFuncAttributeMaxDynamicSharedMemorySize, SMEM_TOTAL);
    k_gemm<<<dim3(NT64, 2), 256, SMEM_TOTAL>>>(b0, b1, out);
    k_final<<<NPIX_ / 256, 256>>>(out);
}

// round 11
// speedup vs baseline: 1.1361x; 1.1361x over previous
#include <cuda_runtime.h>
#include <cuda_bf16.h>
#include <math.h>
#include <stdint.h>

#define B_ 4
#define C_ 256
#define H_ 128
#define W_ 128
#define HW_ (H_*W_)
#define NPIX_ (B_*HW_)
#define NT64 (NPIX_/64)      // 1024 GEMM tiles, 64 pixels each

typedef unsigned int u32;

// ---------------- global scratch ----------------
__device__ float g_xt[(size_t)NPIX_ * C_];                                 // 64 MB
__device__ __align__(16) __nv_bfloat16 gQ[(size_t)NT64 * 2 * 64 * 256];    // 64 MB
__device__ __align__(16) __nv_bfloat16 gX[(size_t)NT64 * 2 * 64 * 256];    // 64 MB
__device__ __align__(16) __nv_bfloat16 gW[2 * 2 * 256 * 256];              // 512 KB
__device__ __align__(16) float gP[(size_t)NPIX_ * 256];                    // 64 MB (parked K)

// ---------------- PTX helpers ----------------
__device__ __forceinline__ u32 smem_u32(const void* p) {
    u32 a; asm("{ .reg .u64 t; cvta.to.shared.u64 t, %1; cvt.u32.u64 %0, t; }"
               : "=r"(a) : "l"(p));
    return a;
}
__device__ __forceinline__ void ldmx4(u32 addr, u32* r) {
    asm volatile("ldmatrix.sync.aligned.m8n8.x4.shared.b16 {%0,%1,%2,%3}, [%4];"
                 : "=r"(r[0]), "=r"(r[1]), "=r"(r[2]), "=r"(r[3]) : "r"(addr));
}
__device__ __forceinline__ void cpa16(u32 dst, const void* src) {
    asm volatile("cp.async.cg.shared.global [%0], [%1], 16;" :: "r"(dst), "l"(src));
}
#define CP_COMMIT() asm volatile("cp.async.commit_group;" ::: "memory")
#define CP_WAIT(n)  asm volatile("cp.async.wait_group %0;" :: "n"(n) : "memory")

__device__ __forceinline__ void mma_bf16(float* d, const u32* a, u32 b0, u32 b1) {
    asm volatile(
        "mma.sync.aligned.m16n8k16.row.col.f32.bf16.bf16.f32 "
        "{%0,%1,%2,%3},{%4,%5,%6,%7},{%8,%9},{%0,%1,%2,%3};"
        : "+f"(d[0]), "+f"(d[1]), "+f"(d[2]), "+f"(d[3])
        : "r"(a[0]), "r"(a[1]), "r"(a[2]), "r"(a[3]), "r"(b0), "r"(b1));
}

// ---------------------------------------------------------------------------
// Transpose x -> g_xt (NHWC fp32) AND gX (bf16 hi/lo, GEMM tile layout)
// ---------------------------------------------------------------------------
__global__ void k_tx(const float* __restrict__ x) {
    __shared__ float t[32][33];
    int b = blockIdx.z, s0 = blockIdx.x * 32, c0 = blockIdx.y * 32;
    int tx = threadIdx.x, ty = threadIdx.y;
    const float* xi = x + (size_t)b * C_ * HW_;
    float* xo = g_xt + (size_t)b * HW_ * C_;
#pragma unroll
    for (int i = 0; i < 32; i += 8)
        t[ty + i][tx] = xi[(size_t)(c0 + ty + i) * HW_ + s0 + tx];
    __syncthreads();
#pragma unroll
    for (int i = 0; i < 32; i += 8) {
        float v = t[tx][ty + i];
        int s = s0 + ty + i;
        xo[(size_t)s * C_ + c0 + tx] = v;
        int gp = b * HW_ + s;
        size_t tb = (size_t)(gp >> 6) * 32768 + (size_t)(gp & 63) * 256 + c0 + tx;
        __nv_bfloat16 h = __float2bfloat16_rn(v);
        gX[tb]         = h;
        gX[tb + 16384] = __float2bfloat16_rn(v - __bfloat162float(h));
    }
}

// ---------------------------------------------------------------------------
// Weight prep: w[o][c] fp32 -> gW[g][plane][o][k] bf16 (hi/lo split)
// ---------------------------------------------------------------------------
__global__ void k_wprep(const float* __restrict__ w0, const float* __restrict__ w1) {
    int g = blockIdx.x;
    int o = threadIdx.x;
    const float* w = g ? w1 : w0;
    __nv_bfloat16* hi = gW + ((size_t)(g * 2 + 0) * 256 + o) * 256;
    __nv_bfloat16* lo = gW + ((size_t)(g * 2 + 1) * 256 + o) * 256;
    for (int k = 0; k < 256; k++) {
        float a = w[o * 256 + k];
        __nv_bfloat16 h = __float2bfloat16_rn(a);
        hi[k] = h;
        lo[k] = __float2bfloat16_rn(a - __bfloat162float(h));
    }
}

// ---------------------------------------------------------------------------
// shared GEMM core: M64 x N256, 256 threads (8 warps 2m x 4n), 3-stage
// cp.async pipeline, split-bf16 3-term accumulation into acc[2][8][4]
// ---------------------------------------------------------------------------
#define ARS 48
#define SOFF_BIAS  0        // 256 f
#define SOFF_STATS 2048     // 4*5*64 f
#define SOFF_A     7168     // 3 stages x 6144 B
#define SOFF_B     25600    // 3 stages x 24576 B
#define SMEM_TOTAL 99328

__device__ __forceinline__ void gemm_core(
    u32 smA, u32 smB, const __nv_bfloat16* Ab, const __nv_bfloat16* Bb,
    int tid, int lane, int mw, int nw, float acc[2][8][4])
{
    const int aPl = tid >> 7, aRow = (tid >> 1) & 63, aHf = tid & 1;
    const u32 aDst0 = smA + aPl * 3072 + aRow * ARS + aHf * 16;
    const __nv_bfloat16* aSrc = Ab + aPl * 16384 + aRow * 256 + aHf * 8;

    const int aLRow = lane & 15, aLCol = (lane >> 4) * 16;
    const int bLRow = ((lane >> 4) << 3) + (lane & 7), bLCol = ((lane >> 3) & 1) * 16;

#pragma unroll
    for (int s = 0; s < 2; s++)
#pragma unroll
        for (int t = 0; t < 8; t++)
#pragma unroll
            for (int j = 0; j < 4; j++) acc[s][t][j] = 0.f;

#pragma unroll
    for (int st = 0; st < 2; st++) {
        cpa16(aDst0 + st * 6144, aSrc + st * 16);
#pragma unroll
        for (int i = 0; i < 4; i++) {
            int idx = tid + i * 256;
            int pl = idx >> 9, row = (idx >> 1) & 255, hf = idx & 1;
            cpa16(smB + st * 24576 + pl * 12288 + row * ARS + hf * 16,
                  Bb + pl * 65536 + row * 256 + st * 16 + hf * 8);
        }
        CP_COMMIT();
    }

    for (int ks = 0; ks < 16; ks++) {
        if (ks < 14) { CP_WAIT(1); } else { CP_WAIT(0); }
        __syncthreads();

        const int cur = ks % 3;
        const u32 Ac = smA + cur * 6144;
        const u32 Bc = smB + cur * 24576;

        u32 ah[2][4], al[2][4];
#pragma unroll
        for (int s = 0; s < 2; s++) {
            u32 arow = (u32)(mw * 32 + s * 16 + aLRow);
            ldmx4(Ac + arow * ARS + aLCol, ah[s]);
            ldmx4(Ac + 3072 + arow * ARS + aLCol, al[s]);
        }
#pragma unroll
        for (int tt = 0; tt < 4; tt++) {
            u32 brow = (u32)(nw * 64 + tt * 16 + bLRow);
            u32 bh[4], bl[4];
            ldmx4(Bc + brow * ARS + bLCol, bh);
            ldmx4(Bc + 12288 + brow * ARS + bLCol, bl);
#pragma unroll
            for (int half = 0; half < 2; half++) {
                int t = tt * 2 + half;
                u32 b0h = bh[half * 2], b1h = bh[half * 2 + 1];
                u32 b0l = bl[half * 2], b1l = bl[half * 2 + 1];
#pragma unroll
                for (int s = 0; s < 2; s++) {
                    mma_bf16(acc[s][t], ah[s], b0h, b1h);
                    mma_bf16(acc[s][t], ah[s], b0l, b1l);
                    mma_bf16(acc[s][t], al[s], b0h, b1h);
                }
            }
        }

        if (ks < 14) {
            const int nst = (ks + 2) % 3;
            cpa16(aDst0 + nst * 6144, aSrc + (ks + 2) * 16);
#pragma unroll
            for (int i = 0; i < 4; i++) {
                int idx = tid + i * 256;
                int pl = idx >> 9, row = (idx >> 1) & 255, hf = idx & 1;
                cpa16(smB + nst * 24576 + pl * 12288 + row * ARS + hf * 16,
                      Bb + pl * 65536 + row * 256 + (ks + 2) * 16 + hf * 8);
            }
            CP_COMMIT();
        }
    }
}

// ---------------------------------------------------------------------------
// split-bf16 store for the gather output
// ---------------------------------------------------------------------------
__device__ __forceinline__ void split_store4(__nv_bfloat16* pHi, __nv_bfloat16* pLo, float4 v) {
    __nv_bfloat16 h0 = __float2bfloat16_rn(v.x), h1 = __float2bfloat16_rn(v.y);
    __nv_bfloat16 h2 = __float2bfloat16_rn(v.z), h3 = __float2bfloat16_rn(v.w);
    __nv_bfloat162 a = __halves2bfloat162(h0, h1), b = __halves2bfloat162(h2, h3);
    __nv_bfloat162 c = __halves2bfloat162(
        __float2bfloat16_rn(v.x - __bfloat162float(h0)),
        __float2bfloat16_rn(v.y - __bfloat162float(h1)));
    __nv_bfloat162 d = __halves2bfloat162(
        __float2bfloat16_rn(v.z - __bfloat162float(h2)),
        __float2bfloat16_rn(v.w - __bfloat162float(h3)));
    uint2 hv, lv;
    hv.x = *(u32*)&a; hv.y = *(u32*)&b;
    lv.x = *(u32*)&c; lv.y = *(u32*)&d;
    *(uint2*)pHi = hv;
    *(uint2*)pLo = lv;
}

// ---------------------------------------------------------------------------
// Fused kernel: 3 blocks per 64-px tile — blocks bx%3 in {0,2} do the
// deformable gather (32 px each), bx%3==1 does the X-GEMM for the tile
// (K = W1 x + b1 parked to gP). Interleaved so each wave carries both
// LSU-bound and tensor-bound work.
// ---------------------------------------------------------------------------
__global__ __launch_bounds__(256, 2)
void k_fused(const float* __restrict__ offset, const float* __restrict__ gb1) {
    extern __shared__ unsigned char sm[];
    const int tid = threadIdx.x, lane = tid & 31, wid = tid >> 5;
    const int bx = blockIdx.x;
    const int m3 = bx % 3;

    if (m3 == 1) {
        // ----- X GEMM tile -----
        const int tile = bx / 3;
        float* bias = (float*)(sm + SOFF_BIAS);
        const u32 smb = smem_u32(sm);
        bias[tid] = gb1[tid];

        float acc[2][8][4];
        gemm_core(smb + SOFF_A, smb + SOFF_B,
                  gX + (size_t)tile * 32768, gW + 131072,
                  tid, lane, wid >> 2, wid & 3, acc);

        float* parkP = gP + (size_t)tile * 64 * 256;
        const int mw = wid >> 2, nw = wid & 3;
#pragma unroll
        for (int s = 0; s < 2; s++) {
            int r1 = mw * 32 + s * 16 + (lane >> 2);
#pragma unroll
            for (int t = 0; t < 8; t++) {
                int n0 = nw * 64 + t * 8 + (lane & 3) * 2;
                float2 v0 = make_float2(acc[s][t][0] + bias[n0], acc[s][t][1] + bias[n0 + 1]);
                float2 v1 = make_float2(acc[s][t][2] + bias[n0], acc[s][t][3] + bias[n0 + 1]);
                *(float2*)(parkP + r1 * 256 + n0) = v0;
                *(float2*)(parkP + (r1 + 8) * 256 + n0) = v1;
            }
        }
        return;
    }

    // ----- gather block: g in [0, NPIX_/32) -----
    const int g = (bx / 3) * 2 + (m3 == 2 ? 1 : 0);
    float* offs = (float*)sm;      // 18*32 floats

    const int base = g * 32;
    const int b    = base / HW_;
    const int rem  = base % HW_;
    const int y    = rem / W_;
    const int x0   = rem % W_;

    for (int i = tid; i < 18 * 32; i += 256) {
        int j = i >> 5, p = i & 31;
        offs[i] = offset[((size_t)b * 18 + j) * HW_ + y * W_ + x0 + p];
    }
    __syncthreads();

    const float* xtb = g_xt + (size_t)b * HW_ * C_;
    const int sub = tid & 7;
    const int p   = tid >> 3;
    const int pxi = x0 + p;
    const int tile = g >> 1;
    const int r    = ((g & 1) << 5) + p;

    float4 qm[8];
#pragma unroll
    for (int i = 0; i < 8; i++) { qm[i].x = qm[i].y = qm[i].z = qm[i].w = -3.4e38f; }

#pragma unroll
    for (int k = 0; k < 9; k++) {
        const int kh = k / 3 - 1, kw = k % 3 - 1;
        float py  = (float)(y + kh)   + offs[(2 * k) * 32 + p];
        float pxx = (float)(pxi + kw) + offs[(2 * k + 1) * 32 + p];
        float fy = floorf(py), fx = floorf(pxx);
        float wy = py - fy, wx = pxx - fx;
        int iy = (int)fy, ix = (int)fx;

        float4 acc[8];
#pragma unroll
        for (int i = 0; i < 8; i++) { acc[i].x = acc[i].y = acc[i].z = acc[i].w = 0.f; }

        float cw[4] = { (1.f - wy) * (1.f - wx), (1.f - wy) * wx,
                        wy * (1.f - wx),         wy * wx };
        int cy[4] = { iy, iy, iy + 1, iy + 1 };
        int cx[4] = { ix, ix + 1, ix, ix + 1 };
#pragma unroll
        for (int c4 = 0; c4 < 4; c4++) {
            if (cy[c4] >= 0 && cy[c4] < H_ && cx[c4] >= 0 && cx[c4] < W_) {
                const float4* cp = (const float4*)(xtb + (size_t)(cy[c4] * W_ + cx[c4]) * C_);
                float w = cw[c4];
#pragma unroll
                for (int i = 0; i < 8; i++) {
                    float4 v = cp[sub + 8 * i];
                    acc[i].x = fmaf(w, v.x, acc[i].x);
                    acc[i].y = fmaf(w, v.y, acc[i].y);
                    acc[i].z = fmaf(w, v.z, acc[i].z);
                    acc[i].w = fmaf(w, v.w, acc[i].w);
                }
            }
        }
#pragma unroll
        for (int i = 0; i < 8; i++) {
            qm[i].x = fmaxf(qm[i].x, acc[i].x);
            qm[i].y = fmaxf(qm[i].y, acc[i].y);
            qm[i].z = fmaxf(qm[i].z, acc[i].z);
            qm[i].w = fmaxf(qm[i].w, acc[i].w);
        }
    }

    size_t tbase = (size_t)tile * 32768 + (size_t)r * 256;
#pragma unroll
    for (int i = 0; i < 8; i++) {
        int c = 4 * (sub + 8 * i);
        split_store4(gQ + tbase + c, gQ + tbase + 16384 + c, qm[i]);
    }
}

// ---------------------------------------------------------------------------
// Q GEMM + full 5-stat epilogue (reads parked K from gP)
// ---------------------------------------------------------------------------
__global__ __launch_bounds__(256, 2)
void k_gemmQ(const float* __restrict__ gb0, float* __restrict__ out) {
    extern __shared__ unsigned char sm[];
    float* bias  = (float*)(sm + SOFF_BIAS);
    float* stats = (float*)(sm + SOFF_STATS);
    const u32 smb = smem_u32(sm);
    const int tid = threadIdx.x, lane = tid & 31, wid = tid >> 5;
    const int mw = wid >> 2, nw = wid & 3;
    const int tile = blockIdx.x;

    bias[tid] = gb0[tid];

    float acc[2][8][4];
    gemm_core(smb + SOFF_A, smb + SOFF_B,
              gQ + (size_t)tile * 32768, gW,
              tid, lane, mw, nw, acc);

    const float* parkP = gP + (size_t)tile * 64 * 256;
#pragma unroll
    for (int s = 0; s < 2; s++) {
        int r1 = mw * 32 + s * 16 + (lane >> 2);
        float st0[5] = {0, 0, 0, 0, 0}, st1[5] = {0, 0, 0, 0, 0};
#pragma unroll
        for (int t = 0; t < 8; t++) {
            int n0 = nw * 64 + t * 8 + (lane & 3) * 2;
            float bq0 = bias[n0], bq1 = bias[n0 + 1];
            float2 k0 = *(const float2*)(parkP + r1 * 256 + n0);
            float2 k1 = *(const float2*)(parkP + (r1 + 8) * 256 + n0);
            float q0x = acc[s][t][0] + bq0, q0y = acc[s][t][1] + bq1;
            float q1x = acc[s][t][2] + bq0, q1y = acc[s][t][3] + bq1;
            st0[0] += q0x + q0y;  st0[1] += k0.x + k0.y;
            st0[2] = fmaf(q0x, q0x, fmaf(q0y, q0y, st0[2]));
            st0[3] = fmaf(k0.x, k0.x, fmaf(k0.y, k0.y, st0[3]));
            st0[4] = fmaf(q0x, k0.x, fmaf(q0y, k0.y, st0[4]));
            st1[0] += q1x + q1y;  st1[1] += k1.x + k1.y;
            st1[2] = fmaf(q1x, q1x, fmaf(q1y, q1y, st1[2]));
            st1[3] = fmaf(k1.x, k1.x, fmaf(k1.y, k1.y, st1[3]));
            st1[4] = fmaf(q1x, k1.x, fmaf(q1y, k1.y, st1[4]));
        }
#pragma unroll
        for (int j = 0; j < 5; j++) {
            st0[j] += __shfl_xor_sync(0xffffffffu, st0[j], 1);
            st0[j] += __shfl_xor_sync(0xffffffffu, st0[j], 2);
            st1[j] += __shfl_xor_sync(0xffffffffu, st1[j], 1);
            st1[j] += __shfl_xor_sync(0xffffffffu, st1[j], 2);
        }
        if ((lane & 3) == 0) {
#pragma unroll
            for (int j = 0; j < 5; j++) {
                stats[(nw * 5 + j) * 64 + r1]     = st0[j];
                stats[(nw * 5 + j) * 64 + r1 + 8] = st1[j];
            }
        }
    }
    __syncthreads();
    if (tid < 64) {
        float sq = 0, sk = 0, sqq = 0, skk = 0, sqk = 0;
#pragma unroll
        for (int w = 0; w < 4; w++) {
            sq  += stats[(w * 5 + 0) * 64 + tid];
            sk  += stats[(w * 5 + 1) * 64 + tid];
            sqq += stats[(w * 5 + 2) * 64 + tid];
            skk += stats[(w * 5 + 3) * 64 + tid];
            sqk += stats[(w * 5 + 4) * 64 + tid];
        }
        const float inv = 1.f / 256.f;
        float num = sqk - sq * sk * inv;
        float dq  = sqq - sq * sq * inv + 1e-5f;
        float dk  = skk - sk * sk * inv + 1e-5f;
        out[tile * 64 + tid] = num * rsqrtf(dq) * rsqrtf(dk);
    }
}

// ---------------------------------------------------------------------------
extern "C" void kernel_launch(void* const* d_in, const int* in_sizes, int n_in,
                              void* d_out, int out_size) {
    const float* x      = (const float*)d_in[0];
    const float* offset = (const float*)d_in[1];
    const float* w0     = (const float*)d_in[2];
    const float* b0     = (const float*)d_in[3];
    const float* w1     = (const float*)d_in[4];
    const float* b1     = (const float*)d_in[5];
    float* out = (float*)d_out;

    k_tx<<<dim3(HW_ / 32, C_ / 32, B_), dim3(32, 8)>>>(x);
    k_wprep<<<2, 256>>>(w0, w1);

    cudaFuncSetAttribute(k_fused, cudaFuncAttributeMaxDynamicSharedMemorySize, SMEM_TOTAL);
    cudaFuncSetAttribute(k_gemmQ, cudaFuncAttributeMaxDynamicSharedMemorySize, SMEM_TOTAL);
    k_fused<<<NT64 * 3, 256, SMEM_TOTAL>>>(offset, b1);
    k_gemmQ<<<NT64, 256, SMEM_TOTAL>>>(b0, out);
}

// round 12
// speedup vs baseline: 1.2030x; 1.0589x over previous
#include <cuda_runtime.h>
#include <cuda_bf16.h>
#include <math.h>
#include <stdint.h>

#define B_ 4
#define C_ 256
#define H_ 128
#define W_ 128
#define HW_ (H_*W_)
#define NPIX_ (B_*HW_)
#define NT64 (NPIX_/64)      // 1024 GEMM tiles, 64 pixels each

typedef unsigned int u32;

// ---------------- global scratch ----------------
__device__ float g_xt[(size_t)NPIX_ * C_];                                 // 64 MB
__device__ __align__(16) __nv_bfloat16 gQ[(size_t)NT64 * 2 * 64 * 256];    // 64 MB
__device__ __align__(16) __nv_bfloat16 gX[(size_t)NT64 * 2 * 64 * 256];    // 64 MB
__device__ __align__(16) __nv_bfloat16 gW[2 * 2 * 256 * 256];              // 512 KB
__device__ __align__(16) float gP[(size_t)NPIX_ * 256];                    // 64 MB (parked K)

// ---------------- PTX helpers ----------------
__device__ __forceinline__ u32 smem_u32(const void* p) {
    u32 a; asm("{ .reg .u64 t; cvta.to.shared.u64 t, %1; cvt.u32.u64 %0, t; }"
               : "=r"(a) : "l"(p));
    return a;
}
__device__ __forceinline__ void ldmx4(u32 addr, u32* r) {
    asm volatile("ldmatrix.sync.aligned.m8n8.x4.shared.b16 {%0,%1,%2,%3}, [%4];"
                 : "=r"(r[0]), "=r"(r[1]), "=r"(r[2]), "=r"(r[3]) : "r"(addr));
}
__device__ __forceinline__ void cpa16(u32 dst, const void* src) {
    asm volatile("cp.async.cg.shared.global [%0], [%1], 16;" :: "r"(dst), "l"(src));
}
#define CP_COMMIT() asm volatile("cp.async.commit_group;" ::: "memory")
#define CP_WAIT(n)  asm volatile("cp.async.wait_group %0;" :: "n"(n) : "memory")

__device__ __forceinline__ void mma_bf16(float* d, const u32* a, u32 b0, u32 b1) {
    asm volatile(
        "mma.sync.aligned.m16n8k16.row.col.f32.bf16.bf16.f32 "
        "{%0,%1,%2,%3},{%4,%5,%6,%7},{%8,%9},{%0,%1,%2,%3};"
        : "+f"(d[0]), "+f"(d[1]), "+f"(d[2]), "+f"(d[3])
        : "r"(a[0]), "r"(a[1]), "r"(a[2]), "r"(a[3]), "r"(b0), "r"(b1));
}

// ---------------------------------------------------------------------------
// Transpose x -> g_xt (NHWC fp32) AND gX (bf16 hi/lo, GEMM tile layout)
// ---------------------------------------------------------------------------
__global__ void k_tx(const float* __restrict__ x) {
    __shared__ float t[32][33];
    int b = blockIdx.z, s0 = blockIdx.x * 32, c0 = blockIdx.y * 32;
    int tx = threadIdx.x, ty = threadIdx.y;
    const float* xi = x + (size_t)b * C_ * HW_;
    float* xo = g_xt + (size_t)b * HW_ * C_;
#pragma unroll
    for (int i = 0; i < 32; i += 8)
        t[ty + i][tx] = xi[(size_t)(c0 + ty + i) * HW_ + s0 + tx];
    __syncthreads();
#pragma unroll
    for (int i = 0; i < 32; i += 8) {
        float v = t[tx][ty + i];
        int s = s0 + ty + i;
        xo[(size_t)s * C_ + c0 + tx] = v;
        int gp = b * HW_ + s;
        size_t tb = (size_t)(gp >> 6) * 32768 + (size_t)(gp & 63) * 256 + c0 + tx;
        __nv_bfloat16 h = __float2bfloat16_rn(v);
        gX[tb]         = h;
        gX[tb + 16384] = __float2bfloat16_rn(v - __bfloat162float(h));
    }
}

// ---------------------------------------------------------------------------
// Weight prep: w[o][c] fp32 -> gW[g][plane][o][k] bf16 (hi/lo split)
// ---------------------------------------------------------------------------
__global__ void k_wprep(const float* __restrict__ w0, const float* __restrict__ w1) {
    int g = blockIdx.x;
    int o = threadIdx.x;
    const float* w = g ? w1 : w0;
    __nv_bfloat16* hi = gW + ((size_t)(g * 2 + 0) * 256 + o) * 256;
    __nv_bfloat16* lo = gW + ((size_t)(g * 2 + 1) * 256 + o) * 256;
    for (int k = 0; k < 256; k++) {
        float a = w[o * 256 + k];
        __nv_bfloat16 h = __float2bfloat16_rn(a);
        hi[k] = h;
        lo[k] = __float2bfloat16_rn(a - __bfloat162float(h));
    }
}

// ---------------------------------------------------------------------------
// shared GEMM core: M64 x N256, 256 threads (8 warps 2m x 4n), 3-stage
// cp.async pipeline, split-bf16 3-term accumulation into acc[2][8][4]
// ---------------------------------------------------------------------------
#define ARS 48
#define SOFF_BIAS  0        // 256 f
#define SOFF_STATS 2048     // 4*5*64 f
#define SOFF_A     7168     // 3 stages x 6144 B
#define SOFF_B     25600    // 3 stages x 24576 B
#define SMEM_TOTAL 99328

__device__ __forceinline__ void gemm_core(
    u32 smA, u32 smB, const __nv_bfloat16* Ab, const __nv_bfloat16* Bb,
    int tid, int lane, int mw, int nw, float acc[2][8][4])
{
    const int aPl = tid >> 7, aRow = (tid >> 1) & 63, aHf = tid & 1;
    const u32 aDst0 = smA + aPl * 3072 + aRow * ARS + aHf * 16;
    const __nv_bfloat16* aSrc = Ab + aPl * 16384 + aRow * 256 + aHf * 8;

    const int aLRow = lane & 15, aLCol = (lane >> 4) * 16;
    const int bLRow = ((lane >> 4) << 3) + (lane & 7), bLCol = ((lane >> 3) & 1) * 16;

#pragma unroll
    for (int s = 0; s < 2; s++)
#pragma unroll
        for (int t = 0; t < 8; t++)
#pragma unroll
            for (int j = 0; j < 4; j++) acc[s][t][j] = 0.f;

#pragma unroll
    for (int st = 0; st < 2; st++) {
        cpa16(aDst0 + st * 6144, aSrc + st * 16);
#pragma unroll
        for (int i = 0; i < 4; i++) {
            int idx = tid + i * 256;
            int pl = idx >> 9, row = (idx >> 1) & 255, hf = idx & 1;
            cpa16(smB + st * 24576 + pl * 12288 + row * ARS + hf * 16,
                  Bb + pl * 65536 + row * 256 + st * 16 + hf * 8);
        }
        CP_COMMIT();
    }

    for (int ks = 0; ks < 16; ks++) {
        if (ks < 14) { CP_WAIT(1); } else { CP_WAIT(0); }
        __syncthreads();

        const int cur = ks % 3;
        const u32 Ac = smA + cur * 6144;
        const u32 Bc = smB + cur * 24576;

        u32 ah[2][4], al[2][4];
#pragma unroll
        for (int s = 0; s < 2; s++) {
            u32 arow = (u32)(mw * 32 + s * 16 + aLRow);
            ldmx4(Ac + arow * ARS + aLCol, ah[s]);
            ldmx4(Ac + 3072 + arow * ARS + aLCol, al[s]);
        }
#pragma unroll
        for (int tt = 0; tt < 4; tt++) {
            u32 brow = (u32)(nw * 64 + tt * 16 + bLRow);
            u32 bh[4], bl[4];
            ldmx4(Bc + brow * ARS + bLCol, bh);
            ldmx4(Bc + 12288 + brow * ARS + bLCol, bl);
#pragma unroll
            for (int half = 0; half < 2; half++) {
                int t = tt * 2 + half;
                u32 b0h = bh[half * 2], b1h = bh[half * 2 + 1];
                u32 b0l = bl[half * 2], b1l = bl[half * 2 + 1];
#pragma unroll
                for (int s = 0; s < 2; s++) {
                    mma_bf16(acc[s][t], ah[s], b0h, b1h);
                    mma_bf16(acc[s][t], ah[s], b0l, b1l);
                    mma_bf16(acc[s][t], al[s], b0h, b1h);
                }
            }
        }

        if (ks < 14) {
            const int nst = (ks + 2) % 3;
            cpa16(aDst0 + nst * 6144, aSrc + (ks + 2) * 16);
#pragma unroll
            for (int i = 0; i < 4; i++) {
                int idx = tid + i * 256;
                int pl = idx >> 9, row = (idx >> 1) & 255, hf = idx & 1;
                cpa16(smB + nst * 24576 + pl * 12288 + row * ARS + hf * 16,
                      Bb + pl * 65536 + row * 256 + (ks + 2) * 16 + hf * 8);
            }
            CP_COMMIT();
        }
    }
}

// ---------------------------------------------------------------------------
// split-bf16 store for the gather output
// ---------------------------------------------------------------------------
__device__ __forceinline__ void split_store4(__nv_bfloat16* pHi, __nv_bfloat16* pLo, float4 v) {
    __nv_bfloat16 h0 = __float2bfloat16_rn(v.x), h1 = __float2bfloat16_rn(v.y);
    __nv_bfloat16 h2 = __float2bfloat16_rn(v.z), h3 = __float2bfloat16_rn(v.w);
    __nv_bfloat162 a = __halves2bfloat162(h0, h1), b = __halves2bfloat162(h2, h3);
    __nv_bfloat162 c = __halves2bfloat162(
        __float2bfloat16_rn(v.x - __bfloat162float(h0)),
        __float2bfloat16_rn(v.y - __bfloat162float(h1)));
    __nv_bfloat162 d = __halves2bfloat162(
        __float2bfloat16_rn(v.z - __bfloat162float(h2)),
        __float2bfloat16_rn(v.w - __bfloat162float(h3)));
    uint2 hv, lv;
    hv.x = *(u32*)&a; hv.y = *(u32*)&b;
    lv.x = *(u32*)&c; lv.y = *(u32*)&d;
    *(uint2*)pHi = hv;
    *(uint2*)pLo = lv;
}

// ---------------------------------------------------------------------------
// Fused kernel: 3 blocks per 64-px tile — blocks bx%3 in {0,2} do the
// deformable gather (32 px each, branch-free batched loads), bx%3==1 does
// the X-GEMM for the tile (K = W1 x + b1 parked to gP).
// ---------------------------------------------------------------------------
__global__ __launch_bounds__(256, 2)
void k_fused(const float* __restrict__ offset, const float* __restrict__ gb1) {
    extern __shared__ unsigned char sm[];
    const int tid = threadIdx.x, lane = tid & 31, wid = tid >> 5;
    const int bx = blockIdx.x;
    const int m3 = bx % 3;

    if (m3 == 1) {
        // ----- X GEMM tile -----
        const int tile = bx / 3;
        float* bias = (float*)(sm + SOFF_BIAS);
        const u32 smb = smem_u32(sm);
        bias[tid] = gb1[tid];

        float acc[2][8][4];
        gemm_core(smb + SOFF_A, smb + SOFF_B,
                  gX + (size_t)tile * 32768, gW + 131072,
                  tid, lane, wid >> 2, wid & 3, acc);

        float* parkP = gP + (size_t)tile * 64 * 256;
        const int mw = wid >> 2, nw = wid & 3;
#pragma unroll
        for (int s = 0; s < 2; s++) {
            int r1 = mw * 32 + s * 16 + (lane >> 2);
#pragma unroll
            for (int t = 0; t < 8; t++) {
                int n0 = nw * 64 + t * 8 + (lane & 3) * 2;
                float2 v0 = make_float2(acc[s][t][0] + bias[n0], acc[s][t][1] + bias[n0 + 1]);
                float2 v1 = make_float2(acc[s][t][2] + bias[n0], acc[s][t][3] + bias[n0 + 1]);
                *(float2*)(parkP + r1 * 256 + n0) = v0;
                *(float2*)(parkP + (r1 + 8) * 256 + n0) = v1;
            }
        }
        return;
    }

    // ----- gather block: g in [0, NPIX_/32) -----
    const int g = (bx / 3) * 2 + (m3 == 2 ? 1 : 0);
    int*   cidx = (int*)sm;                      // [9][4][32] clamped element offsets
    float* cwt  = (float*)(sm + 4608);           // [9][4][32] validity-zeroed weights

    const int base = g * 32;
    const int b    = base / HW_;
    const int rem  = base % HW_;
    const int y    = rem / W_;
    const int x0   = rem % W_;

    // precompute corner tables (branchless main loop reads these)
    {
        int kk = tid >> 5, pp = tid & 31;
#pragma unroll
        for (int rep = 0; rep < 2; rep++) {
            if (rep == 1) { if (tid >= 32) break; kk = 8; pp = tid; }
            float py  = (float)(y + kk / 3 - 1) +
                offset[((size_t)b * 18 + 2 * kk) * HW_ + y * W_ + x0 + pp];
            float pxx = (float)(x0 + pp + kk % 3 - 1) +
                offset[((size_t)b * 18 + 2 * kk + 1) * HW_ + y * W_ + x0 + pp];
            float fy = floorf(py), fx = floorf(pxx);
            float wy = py - fy, wx = pxx - fx;
            int iy = (int)fy, ix = (int)fx;
            float cw[4] = { (1.f - wy) * (1.f - wx), (1.f - wy) * wx,
                            wy * (1.f - wx),         wy * wx };
            int cy[4] = { iy, iy, iy + 1, iy + 1 };
            int cx[4] = { ix, ix + 1, ix, ix + 1 };
#pragma unroll
            for (int j = 0; j < 4; j++) {
                bool valid = (cy[j] >= 0) & (cy[j] < H_) & (cx[j] >= 0) & (cx[j] < W_);
                int yc = min(max(cy[j], 0), H_ - 1);
                int xc = min(max(cx[j], 0), W_ - 1);
                cidx[(kk * 4 + j) * 32 + pp] = (yc * W_ + xc) * C_;
                cwt [(kk * 4 + j) * 32 + pp] = valid ? cw[j] : 0.f;
            }
        }
    }
    __syncthreads();

    const float* xtb = g_xt + (size_t)b * HW_ * C_;
    const int sub = tid & 7;
    const int p   = tid >> 3;
    const int tile = g >> 1;
    const int r    = ((g & 1) << 5) + p;

    float4 qm[8];
#pragma unroll
    for (int i = 0; i < 8; i++) { qm[i].x = qm[i].y = qm[i].z = qm[i].w = -3.4e38f; }

#pragma unroll
    for (int k = 0; k < 9; k++) {
        const float4* p0 = (const float4*)(xtb + cidx[(k * 4 + 0) * 32 + p]);
        const float4* p1 = (const float4*)(xtb + cidx[(k * 4 + 1) * 32 + p]);
        const float4* p2 = (const float4*)(xtb + cidx[(k * 4 + 2) * 32 + p]);
        const float4* p3 = (const float4*)(xtb + cidx[(k * 4 + 3) * 32 + p]);
        float w0 = cwt[(k * 4 + 0) * 32 + p];
        float w1 = cwt[(k * 4 + 1) * 32 + p];
        float w2 = cwt[(k * 4 + 2) * 32 + p];
        float w3 = cwt[(k * 4 + 3) * 32 + p];
#pragma unroll
        for (int i = 0; i < 8; i++) {
            int ci = sub + 8 * i;
            float4 v0 = p0[ci], v1 = p1[ci], v2 = p2[ci], v3 = p3[ci];
            float ax = w0 * v0.x, ay = w0 * v0.y, az = w0 * v0.z, aw = w0 * v0.w;
            ax = fmaf(w1, v1.x, ax); ay = fmaf(w1, v1.y, ay);
            az = fmaf(w1, v1.z, az); aw = fmaf(w1, v1.w, aw);
            ax = fmaf(w2, v2.x, ax); ay = fmaf(w2, v2.y, ay);
            az = fmaf(w2, v2.z, az); aw = fmaf(w2, v2.w, aw);
            ax = fmaf(w3, v3.x, ax); ay = fmaf(w3, v3.y, ay);
            az = fmaf(w3, v3.z, az); aw = fmaf(w3, v3.w, aw);
            qm[i].x = fmaxf(qm[i].x, ax);
            qm[i].y = fmaxf(qm[i].y, ay);
            qm[i].z = fmaxf(qm[i].z, az);
            qm[i].w = fmaxf(qm[i].w, aw);
        }
    }

    size_t tbase = (size_t)tile * 32768 + (size_t)r * 256;
#pragma unroll
    for (int i = 0; i < 8; i++) {
        int c = 4 * (sub + 8 * i);
        split_store4(gQ + tbase + c, gQ + tbase + 16384 + c, qm[i]);
    }
}

// ---------------------------------------------------------------------------
// Q GEMM + full 5-stat epilogue (reads parked K from gP)
// ---------------------------------------------------------------------------
__global__ __launch_bounds__(256, 2)
void k_gemmQ(const float* __restrict__ gb0, float* __restrict__ out) {
    extern __shared__ unsigned char sm[];
    float* bias  = (float*)(sm + SOFF_BIAS);
    float* stats = (float*)(sm + SOFF_STATS);
    const u32 smb = smem_u32(sm);
    const int tid = threadIdx.x, lane = tid & 31, wid = tid >> 5;
    const int mw = wid >> 2, nw = wid & 3;
    const int tile = blockIdx.x;

    bias[tid] = gb0[tid];

    float acc[2][8][4];
    gemm_core(smb + SOFF_A, smb + SOFF_B,
              gQ + (size_t)tile * 32768, gW,
              tid, lane, mw, nw, acc);

    const float* parkP = gP + (size_t)tile * 64 * 256;
#pragma unroll
    for (int s = 0; s < 2; s++) {
        int r1 = mw * 32 + s * 16 + (lane >> 2);
        float st0[5] = {0, 0, 0, 0, 0}, st1[5] = {0, 0, 0, 0, 0};
#pragma unroll
        for (int t = 0; t < 8; t++) {
            int n0 = nw * 64 + t * 8 + (lane & 3) * 2;
            float bq0 = bias[n0], bq1 = bias[n0 + 1];
            float2 k0 = *(const float2*)(parkP + r1 * 256 + n0);
            float2 k1 = *(const float2*)(parkP + (r1 + 8) * 256 + n0);
            float q0x = acc[s][t][0] + bq0, q0y = acc[s][t][1] + bq1;
            float q1x = acc[s][t][2] + bq0, q1y = acc[s][t][3] + bq1;
            st0[0] += q0x + q0y;  st0[1] += k0.x + k0.y;
            st0[2] = fmaf(q0x, q0x, fmaf(q0y, q0y, st0[2]));
            st0[3] = fmaf(k0.x, k0.x, fmaf(k0.y, k0.y, st0[3]));
            st0[4] = fmaf(q0x, k0.x, fmaf(q0y, k0.y, st0[4]));
            st1[0] += q1x + q1y;  st1[1] += k1.x + k1.y;
            st1[2] = fmaf(q1x, q1x, fmaf(q1y, q1y, st1[2]));
            st1[3] = fmaf(k1.x, k1.x, fmaf(k1.y, k1.y, st1[3]));
            st1[4] = fmaf(q1x, k1.x, fmaf(q1y, k1.y, st1[4]));
        }
#pragma unroll
        for (int j = 0; j < 5; j++) {
            st0[j] += __shfl_xor_sync(0xffffffffu, st0[j], 1);
            st0[j] += __shfl_xor_sync(0xffffffffu, st0[j], 2);
            st1[j] += __shfl_xor_sync(0xffffffffu, st1[j], 1);
            st1[j] += __shfl_xor_sync(0xffffffffu, st1[j], 2);
        }
        if ((lane & 3) == 0) {
#pragma unroll
            for (int j = 0; j < 5; j++) {
                stats[(nw * 5 + j) * 64 + r1]     = st0[j];
                stats[(nw * 5 + j) * 64 + r1 + 8] = st1[j];
            }
        }
    }
    __syncthreads();
    if (tid < 64) {
        float sq = 0, sk = 0, sqq = 0, skk = 0, sqk = 0;
#pragma unroll
        for (int w = 0; w < 4; w++) {
            sq  += stats[(w * 5 + 0) * 64 + tid];
            sk  += stats[(w * 5 + 1) * 64 + tid];
            sqq += stats[(w * 5 + 2) * 64 + tid];
            skk += stats[(w * 5 + 3) * 64 + tid];
            sqk += stats[(w * 5 + 4) * 64 + tid];
        }
        const float inv = 1.f / 256.f;
        float num = sqk - sq * sk * inv;
        float dq  = sqq - sq * sq * inv + 1e-5f;
        float dk  = skk - sk * sk * inv + 1e-5f;
        out[tile * 64 + tid] = num * rsqrtf(dq) * rsqrtf(dk);
    }
}

// ---------------------------------------------------------------------------
extern "C" void kernel_launch(void* const* d_in, const int* in_sizes, int n_in,
                              void* d_out, int out_size) {
    const float* x      = (const float*)d_in[0];
    const float* offset = (const float*)d_in[1];
    const float* w0     = (const float*)d_in[2];
    const float* b0     = (const float*)d_in[3];
    const float* w1     = (const float*)d_in[4];
    const float* b1     = (const float*)d_in[5];
    float* out = (float*)d_out;

    k_tx<<<dim3(HW_ / 32, C_ / 32, B_), dim3(32, 8)>>>(x);
    k_wprep<<<2, 256>>>(w0, w1);

    cudaFuncSetAttribute(k_fused, cudaFuncAttributeMaxDynamicSharedMemorySize, SMEM_TOTAL);
    cudaFuncSetAttribute(k_gemmQ, cudaFuncAttributeMaxDynamicSharedMemorySize, SMEM_TOTAL);
    k_fused<<<NT64 * 3, 256, SMEM_TOTAL>>>(offset, b1);
    k_gemmQ<<<NT64, 256, SMEM_TOTAL>>>(b0, out);
}